// round 11
// baseline (speedup 1.0000x reference)
#include <cuda_runtime.h>
#include <cuda_fp16.h>
#include <cstdint>

// out[b, de] = sum_k w[b,k] * A[k, de], A diagonal (de % 257 == 0) zeroed for all k.
// W: (2048, 32) f32   A: (32, 65536) f32   Out: (2048, 65536) f32
//
// fp16 HMMA (m16n8k16, fp32 accum) + TMA bulk-store epilogue:
//   CTA: 256 batch x 128 de, 8 warps; warp: 32 batch x 128 de.
//   Per m16 group (16 rows): compute 4 chunks x 4 n8-frags, stage rows into a
//   528B-pitch smem buffer (STS.64 conflict-free, rows contiguous 512B), then
//   lanes 0-15 each issue cp.async.bulk (512B) -> L2/DRAM with ZERO LSU cost.
//   Group-0 TMA drain overlaps group-1 compute. 2 CTAs/SM.

#define DE   65536
#define KD   32
#define TDE  128     // de per CTA
#define TB   256     // batch per CTA
#define NB   2048
#define ASTRIDE 20   // uint32 row stride for A tile (conflict-free LDS.32)
#define SPITCH  132  // floats per staged row (528 B; 528/8 mod 16 = 2 -> no conflicts)

// dynamic smem layout (bytes)
#define SM_AH    0
#define SM_STAGE (TDE * ASTRIDE * 4)                      // 10240
#define SM_WARPB (16 * SPITCH * 4)                        // 8448 per warp
#define SM_TOTAL (SM_STAGE + 8 * SM_WARPB)                // 77824

static __device__ __forceinline__ uint32_t pack_h2(float e0, float e1) {
    __half2 h = __floats2half2_rn(e0, e1);
    return *(uint32_t*)&h;
}

static __device__ __forceinline__ void mma16816(float* d, const uint32_t* a,
                                                uint32_t b0, uint32_t b1) {
    asm volatile(
        "mma.sync.aligned.m16n8k16.row.col.f32.f16.f16.f32 "
        "{%0,%1,%2,%3}, {%4,%5,%6,%7}, {%8,%9}, {%0,%1,%2,%3};"
        : "+f"(d[0]), "+f"(d[1]), "+f"(d[2]), "+f"(d[3])
        : "r"(a[0]), "r"(a[1]), "r"(a[2]), "r"(a[3]), "r"(b0), "r"(b1));
}

static __device__ __forceinline__ uint32_t smem_u32(const void* p) {
    uint32_t a;
    asm("{ .reg .u64 t; cvta.to.shared.u64 t, %1; cvt.u32.u64 %0, t; }" : "=r"(a) : "l"(p));
    return a;
}

__global__ __launch_bounds__(256, 2)
void explainer_hmma(const float* __restrict__ w,
                    const float* __restrict__ A,
                    float* __restrict__ out) {
    extern __shared__ char smem[];
    uint32_t* Ah = (uint32_t*)(smem + SM_AH);

    const int tid = threadIdx.x;
    const int de0 = blockIdx.x * TDE;
    const int b0  = blockIdx.y * TB;

    // ---- Load A tile: 128 de x 16 k-pairs, fp16 packed, diagonal masked ----
    #pragma unroll
    for (int i = 0; i < 8; i++) {
        int idx = tid + i * 256;        // 0..2047
        int p   = idx >> 7;             // k-pair 0..15
        int de  = idx & 127;
        int k0  = p << 1;
        float v0 = A[(size_t)k0 * DE + de0 + de];
        float v1 = A[(size_t)(k0 + 1) * DE + de0 + de];
        if (((de0 + de) % 257) == 0) { v0 = 0.0f; v1 = 0.0f; }
        Ah[de * ASTRIDE + p] = pack_h2(v0, v1);
    }

    // ---- W fragments in registers: warp covers 32 batches (2 m16 groups) ----
    const int warp = tid >> 5;
    const int lane = tid & 31;
    const int qr = lane >> 2;   // 0..7
    const int qc = lane & 3;    // 0..3
    const int mb = b0 + warp * 32;

    uint32_t whi[2][2][4];      // [m-group][k-step][a-reg]
    #pragma unroll
    for (int g = 0; g < 2; g++) {
        #pragma unroll
        for (int s = 0; s < 2; s++) {
            #pragma unroll
            for (int h = 0; h < 2; h++) {
                #pragma unroll
                for (int rr = 0; rr < 2; rr++) {
                    int row = mb + g * 16 + qr + rr * 8;
                    int kk  = s * 16 + 2 * qc + h * 8;
                    float2 v = *(const float2*)&w[(size_t)row * KD + kk];
                    whi[g][s][rr + 2 * h] = pack_h2(v.x, v.y);
                }
            }
        }
    }
    __syncthreads();

    float* Sw = (float*)(smem + SM_STAGE + warp * SM_WARPB);
    const uint32_t sw_u32 = smem_u32(Sw);

    // ---- Per m16 group: compute 16 rows x 128 de, stage, TMA-drain ----
    #pragma unroll 1
    for (int g = 0; g < 2; g++) {
        if (g) {
            // group-0 copies must have left the buffer before restaging
            if (lane < 16) {
                asm volatile("cp.async.bulk.wait_group 0;" ::: "memory");
            }
            __syncwarp();
        }

        #pragma unroll
        for (int c = 0; c < 4; c++) {
            float dd[4][4];
            #pragma unroll
            for (int f = 0; f < 4; f++) {
                int fc = c * 4 + f;
                const uint32_t* ar = &Ah[(fc * 8 + qr) * ASTRIDE];
                uint32_t bh00 = ar[qc],     bh01 = ar[qc + 4];
                uint32_t bh10 = ar[8 + qc], bh11 = ar[12 + qc];

                dd[f][0] = 0.f; dd[f][1] = 0.f; dd[f][2] = 0.f; dd[f][3] = 0.f;
                mma16816(dd[f], whi[g][0], bh00, bh01);   // k-step 0
                mma16816(dd[f], whi[g][1], bh10, bh11);   // k-step 1
            }
            // stage: rows qr and qr+8 of this group, cols c*32 + f*8 + 2qc
            #pragma unroll
            for (int f = 0; f < 4; f++) {
                int col = c * 32 + f * 8 + 2 * qc;
                *(float2*)&Sw[qr * SPITCH + col] = make_float2(dd[f][0], dd[f][1]);
                *(float2*)&Sw[(qr + 8) * SPITCH + col] = make_float2(dd[f][2], dd[f][3]);
            }
        }

        __syncwarp();
        asm volatile("fence.proxy.async.shared::cta;" ::: "memory");

        // lanes 0-15: one 512B bulk copy per row (contiguous, 16B aligned)
        if (lane < 16) {
            float* gdst = out + (size_t)(mb + g * 16 + lane) * DE + de0;
            uint32_t ssrc = sw_u32 + (uint32_t)(lane * SPITCH * 4);
            asm volatile(
                "cp.async.bulk.global.shared::cta.bulk_group [%0], [%1], %2;"
                :: "l"(gdst), "r"(ssrc), "r"(512) : "memory");
            asm volatile("cp.async.bulk.commit_group;" ::: "memory");
        }
    }

    // drain outstanding bulk stores before exit
    if (lane < 16) {
        asm volatile("cp.async.bulk.wait_group 0;" ::: "memory");
    }
}

extern "C" void kernel_launch(void* const* d_in, const int* in_sizes, int n_in,
                              void* d_out, int out_size) {
    const float* w = (const float*)d_in[0];   // batch_weights (2048, 32)
    const float* A = (const float*)d_in[1];   // archs (32, 256, 256)
    float* out = (float*)d_out;               // (2048, 256, 256) f32

    cudaFuncSetAttribute(explainer_hmma, cudaFuncAttributeMaxDynamicSharedMemorySize,
                         SM_TOTAL);
    dim3 grid(DE / TDE, NB / TB);             // (512, 8)
    explainer_hmma<<<grid, 256, SM_TOTAL>>>(w, A, out);
}

// round 12
// speedup vs baseline: 1.2425x; 1.2425x over previous
#include <cuda_runtime.h>
#include <cuda_fp16.h>
#include <cstdint>

// out[b, de] = sum_k w[b,k] * A[k, de], A diagonal (de % 257 == 0) zeroed for all k.
// W: (2048, 32) f32   A: (32, 65536) f32   Out: (2048, 65536) f32
//
// fp16 HMMA (m16n8k16, fp32 accum) with PERMUTED de->fragment-column mapping:
//   de_local = 32q + 8t + 2u + v stored at frag (4q+u), B-col (2t+v).
//   => thread qc's accumulators across a frag-quad are 8 CONTIGUOUS de per row,
//   stored with st.global.cs.v8.b32 (256-bit): 8 full 128B lines per instr,
//   no smem staging round-trip at all.
//   CTA: 256 batch x 128 de, 8 warps; warp: 32 batch x 128 de. 3 CTAs/SM.

#define DE   65536
#define KD   32
#define TDE  128     // de per CTA
#define TB   256     // batch per CTA
#define NB   2048
#define ASTRIDE 20   // uint32 row stride for A tile (conflict-free LDS.32)

#define SM_TOTAL (TDE * ASTRIDE * 4)   // 10240 bytes: A tile only

static __device__ __forceinline__ uint32_t pack_h2(float e0, float e1) {
    __half2 h = __floats2half2_rn(e0, e1);
    return *(uint32_t*)&h;
}

static __device__ __forceinline__ void mma16816(float* d, const uint32_t* a,
                                                uint32_t b0, uint32_t b1) {
    asm volatile(
        "mma.sync.aligned.m16n8k16.row.col.f32.f16.f16.f32 "
        "{%0,%1,%2,%3}, {%4,%5,%6,%7}, {%8,%9}, {%0,%1,%2,%3};"
        : "+f"(d[0]), "+f"(d[1]), "+f"(d[2]), "+f"(d[3])
        : "r"(a[0]), "r"(a[1]), "r"(a[2]), "r"(a[3]), "r"(b0), "r"(b1));
}

static __device__ __forceinline__ void stg_v8(float* p,
                                              float a0, float a1, float a2, float a3,
                                              float a4, float a5, float a6, float a7) {
    asm volatile(
        "st.global.cs.v8.b32 [%0], {%1,%2,%3,%4,%5,%6,%7,%8};"
        :: "l"(p),
           "r"(__float_as_uint(a0)), "r"(__float_as_uint(a1)),
           "r"(__float_as_uint(a2)), "r"(__float_as_uint(a3)),
           "r"(__float_as_uint(a4)), "r"(__float_as_uint(a5)),
           "r"(__float_as_uint(a6)), "r"(__float_as_uint(a7))
        : "memory");
}

__global__ __launch_bounds__(256, 3)
void explainer_hmma(const float* __restrict__ w,
                    const float* __restrict__ A,
                    float* __restrict__ out) {
    extern __shared__ char smem[];
    uint32_t* Ah = (uint32_t*)smem;

    const int tid = threadIdx.x;
    const int de0 = blockIdx.x * TDE;
    const int b0  = blockIdx.y * TB;

    // ---- Load A tile: 128 de x 16 k-pairs, fp16 packed, diagonal masked ----
    // Slot permutation: de = 32q + 8t + 2u + v  ->  slot_row = 32q + 8u + 2t + v
    #pragma unroll
    for (int i = 0; i < 8; i++) {
        int idx = tid + i * 256;        // 0..2047
        int p   = idx >> 7;             // k-pair 0..15
        int de  = idx & 127;
        int k0  = p << 1;
        float v0 = A[(size_t)k0 * DE + de0 + de];
        float v1 = A[(size_t)(k0 + 1) * DE + de0 + de];
        if (((de0 + de) % 257) == 0) { v0 = 0.0f; v1 = 0.0f; }
        int q = de >> 5;
        int t = (de >> 3) & 3;
        int u = (de >> 1) & 3;
        int v = de & 1;
        int slot = 32 * q + 8 * u + 2 * t + v;
        Ah[slot * ASTRIDE + p] = pack_h2(v0, v1);
    }

    // ---- W fragments in registers: warp covers 32 batches (2 m16 groups) ----
    const int warp = tid >> 5;
    const int lane = tid & 31;
    const int qr = lane >> 2;   // 0..7
    const int qc = lane & 3;    // 0..3
    const int mb = b0 + warp * 32;

    uint32_t whi[2][2][4];      // [m-group][k-step][a-reg]
    #pragma unroll
    for (int g = 0; g < 2; g++) {
        #pragma unroll
        for (int s = 0; s < 2; s++) {
            #pragma unroll
            for (int h = 0; h < 2; h++) {
                #pragma unroll
                for (int rr = 0; rr < 2; rr++) {
                    int row = mb + g * 16 + qr + rr * 8;
                    int kk  = s * 16 + 2 * qc + h * 8;
                    float2 v = *(const float2*)&w[(size_t)row * KD + kk];
                    whi[g][s][rr + 2 * h] = pack_h2(v.x, v.y);
                }
            }
        }
    }
    __syncthreads();

    // ---- Main loop: 4 frag-quads of 32 de each ----
    #pragma unroll 1
    for (int q = 0; q < 4; q++) {
        // Load B fragments for the quad once (reused by both m-groups)
        uint32_t bq[4][4];
        #pragma unroll
        for (int u = 0; u < 4; u++) {
            const uint32_t* ar = &Ah[(32 * q + 8 * u + qr) * ASTRIDE];
            bq[u][0] = ar[qc];     bq[u][1] = ar[qc + 4];
            bq[u][2] = ar[8 + qc]; bq[u][3] = ar[12 + qc];
        }

        #pragma unroll
        for (int g = 0; g < 2; g++) {
            float dd[4][4];
            #pragma unroll
            for (int u = 0; u < 4; u++) {
                dd[u][0] = 0.f; dd[u][1] = 0.f; dd[u][2] = 0.f; dd[u][3] = 0.f;
                mma16816(dd[u], whi[g][0], bq[u][0], bq[u][1]);   // k-step 0
                mma16816(dd[u], whi[g][1], bq[u][2], bq[u][3]);   // k-step 1
            }

            // Rows qr and qr+8: 8 contiguous de starting at 32q + 8qc
            size_t r0 = (size_t)(mb + g * 16 + qr);
            float* p0 = out + r0 * DE + de0 + 32 * q + 8 * qc;
            stg_v8(p0, dd[0][0], dd[0][1], dd[1][0], dd[1][1],
                       dd[2][0], dd[2][1], dd[3][0], dd[3][1]);
            float* p1 = out + (r0 + 8) * DE + de0 + 32 * q + 8 * qc;
            stg_v8(p1, dd[0][2], dd[0][3], dd[1][2], dd[1][3],
                       dd[2][2], dd[2][3], dd[3][2], dd[3][3]);
        }
    }
}

extern "C" void kernel_launch(void* const* d_in, const int* in_sizes, int n_in,
                              void* d_out, int out_size) {
    const float* w = (const float*)d_in[0];   // batch_weights (2048, 32)
    const float* A = (const float*)d_in[1];   // archs (32, 256, 256)
    float* out = (float*)d_out;               // (2048, 256, 256) f32

    cudaFuncSetAttribute(explainer_hmma, cudaFuncAttributeMaxDynamicSharedMemorySize,
                         SM_TOTAL);
    dim3 grid(DE / TDE, NB / TB);             // (512, 8)
    explainer_hmma<<<grid, 256, SM_TOTAL>>>(w, A, out);
}